// round 1
// baseline (speedup 1.0000x reference)
#include <cuda_runtime.h>
#include <math.h>

#define BSZ 4
#define SEQ 2048
#define DIM 512
#define NHEAD 8
#define HD 64
#define NEGV (-1e23f)
#define ATT_SCALE 0.044194173824159216f   // 1/sqrt(512)

// Scratch (static device globals: allocation-free)
__device__ float g_Q [BSZ*SEQ*DIM];
__device__ float g_KV[BSZ*SEQ*DIM];
__device__ float g_A [BSZ*SEQ*DIM];

// ---------------------------------------------------------------------------
// Fused Q / KV projection GEMM: C = A(8192x512) @ B(512x512) + bias
// blockIdx.z = 0 -> Q, 1 -> KV.  128x128x8 blocking, 8x8 microtile, 256 thr.
// ---------------------------------------------------------------------------
__global__ __launch_bounds__(256) void gemm_qkv(
    const float* __restrict__ M1, const float* __restrict__ M2,
    const float* __restrict__ Wq, const float* __restrict__ bq,
    const float* __restrict__ Wkv, const float* __restrict__ bkv)
{
    const float* A; const float* B; const float* bias; float* C;
    if (blockIdx.z == 0) { A = M1; B = Wq;  bias = bq;  C = g_Q;  }
    else                 { A = M2; B = Wkv; bias = bkv; C = g_KV; }

    __shared__ float As[8][128];   // [k][m]
    __shared__ float Bs[8][128];   // [k][n]

    const int tid = threadIdx.x;
    const int tx = tid & 15, ty = tid >> 4;
    const int m0 = blockIdx.y * 128, n0 = blockIdx.x * 128;

    float acc[8][8];
    #pragma unroll
    for (int i = 0; i < 8; i++)
        #pragma unroll
        for (int j = 0; j < 8; j++) acc[i][j] = 0.f;

    const int arow = tid >> 1;           // 0..127
    const int acol = (tid & 1) * 4;      // 0 or 4
    const int brow = tid >> 5;           // 0..7
    const int bcol = (tid & 31) * 4;     // 0..124
    const float* Aptr = A + (m0 + arow) * DIM + acol;
    const float* Bptr = B + brow * DIM + n0 + bcol;

    for (int k0 = 0; k0 < DIM; k0 += 8) {
        float4 av = *(const float4*)(Aptr + k0);
        float4 bv = *(const float4*)(Bptr + (size_t)k0 * DIM);
        __syncthreads();
        As[acol + 0][arow] = av.x;
        As[acol + 1][arow] = av.y;
        As[acol + 2][arow] = av.z;
        As[acol + 3][arow] = av.w;
        *(float4*)&Bs[brow][bcol] = bv;
        __syncthreads();
        #pragma unroll
        for (int kk = 0; kk < 8; kk++) {
            float af[8], bf[8];
            *(float4*)&af[0] = *(const float4*)&As[kk][ty * 8];
            *(float4*)&af[4] = *(const float4*)&As[kk][ty * 8 + 4];
            *(float4*)&bf[0] = *(const float4*)&Bs[kk][tx * 8];
            *(float4*)&bf[4] = *(const float4*)&Bs[kk][tx * 8 + 4];
            #pragma unroll
            for (int i = 0; i < 8; i++)
                #pragma unroll
                for (int j = 0; j < 8; j++)
                    acc[i][j] += af[i] * bf[j];
        }
    }

    float bfrag[8];
    *(float4*)&bfrag[0] = *(const float4*)&bias[n0 + tx * 8];
    *(float4*)&bfrag[4] = *(const float4*)&bias[n0 + tx * 8 + 4];
    #pragma unroll
    for (int i = 0; i < 8; i++) {
        float* cp = C + (size_t)(m0 + ty * 8 + i) * DIM + n0 + tx * 8;
        float4 v0 = make_float4(acc[i][0] + bfrag[0], acc[i][1] + bfrag[1],
                                acc[i][2] + bfrag[2], acc[i][3] + bfrag[3]);
        float4 v1 = make_float4(acc[i][4] + bfrag[4], acc[i][5] + bfrag[5],
                                acc[i][6] + bfrag[6], acc[i][7] + bfrag[7]);
        *(float4*)cp       = v0;
        *(float4*)(cp + 4) = v1;
    }
}

// ---------------------------------------------------------------------------
// Flash attention. One block = (batch b, head h, 64 query rows).
// K tile (64 keys) kept in smem BOTH d-major (for Q@K^T) and row-major
// (for P@K, since v=k). 256 threads, each owns a 4x4 tile of S/P and O.
// ---------------------------------------------------------------------------
#define WP 68
#define ATT_SMEM ((4 * 64 * WP + 64) * 4)

__global__ __launch_bounds__(256) void attn_kernel(
    const int* __restrict__ um1, const int* __restrict__ um2)
{
    extern __shared__ float sm[];
    float (*Qt)[WP] = (float(*)[WP])(sm);              // [d][r]
    float (*Kt)[WP] = (float(*)[WP])(sm + 64 * WP);    // [d][c]
    float (*Kr)[WP] = (float(*)[WP])(sm + 2 * 64 * WP);// [c][d]
    float (*Ps)[WP] = (float(*)[WP])(sm + 3 * 64 * WP);// [r][c]
    float* m2s = sm + 4 * 64 * WP;                     // [64]

    const int b = blockIdx.z, h = blockIdx.y, qt = blockIdx.x;
    const int tid = threadIdx.x;
    const int tx = tid & 15, ty = tid >> 4;

    const float* Qg = g_Q  + (size_t)(b * SEQ + qt * 64) * DIM + h * HD;
    const float* Kg = g_KV + (size_t)(b * SEQ) * DIM + h * HD;

    // Load Q tile transposed: Qt[d][r]
    {
        const int f4 = tid & 15;
        const int rb = tid >> 4;
        #pragma unroll
        for (int it = 0; it < 4; it++) {
            int r = rb + it * 16;
            float4 v = *(const float4*)(Qg + (size_t)r * DIM + f4 * 4);
            Qt[f4 * 4 + 0][r] = v.x;
            Qt[f4 * 4 + 1][r] = v.y;
            Qt[f4 * 4 + 2][r] = v.z;
            Qt[f4 * 4 + 3][r] = v.w;
        }
    }

    bool rv[4];
    #pragma unroll
    for (int i = 0; i < 4; i++)
        rv[i] = um1[b * SEQ + qt * 64 + ty * 4 + i] != 0;

    float m_run[4], l_run[4], o[4][4];
    #pragma unroll
    for (int i = 0; i < 4; i++) {
        m_run[i] = -INFINITY;
        l_run[i] = 0.f;
        #pragma unroll
        for (int j = 0; j < 4; j++) o[i][j] = 0.f;
    }

    for (int kt = 0; kt < SEQ / 64; kt++) {
        __syncthreads();   // previous tile's reads of Kr/Kt/Ps are done
        {
            const int f4 = tid & 15;
            const int cb = tid >> 4;
            const float* Kp = Kg + (size_t)(kt * 64) * DIM;
            #pragma unroll
            for (int it = 0; it < 4; it++) {
                int c = cb + it * 16;
                float4 v = *(const float4*)(Kp + (size_t)c * DIM + f4 * 4);
                *(float4*)&Kr[c][f4 * 4] = v;
                Kt[f4 * 4 + 0][c] = v.x;
                Kt[f4 * 4 + 1][c] = v.y;
                Kt[f4 * 4 + 2][c] = v.z;
                Kt[f4 * 4 + 3][c] = v.w;
            }
        }
        if (tid < 64)
            m2s[tid] = (um2[b * SEQ + kt * 64 + tid] != 0) ? 0.0f : NEGV;
        __syncthreads();

        // ---- S = Q @ K^T (frag loads are contiguous float4) ----
        float s[4][4];
        #pragma unroll
        for (int i = 0; i < 4; i++)
            #pragma unroll
            for (int j = 0; j < 4; j++) s[i][j] = 0.f;

        #pragma unroll 4
        for (int d = 0; d < 64; d += 4) {
            float qf[4][4], kf[4][4];
            #pragma unroll
            for (int u = 0; u < 4; u++) {
                *(float4*)&qf[u][0] = *(const float4*)&Qt[d + u][ty * 4];
                *(float4*)&kf[u][0] = *(const float4*)&Kt[d + u][tx * 4];
            }
            #pragma unroll
            for (int u = 0; u < 4; u++)
                #pragma unroll
                for (int i = 0; i < 4; i++)
                    #pragma unroll
                    for (int j = 0; j < 4; j++)
                        s[i][j] += qf[u][i] * kf[u][j];
        }

        // ---- mask + online softmax ----
        float corr[4], rs[4];
        #pragma unroll
        for (int i = 0; i < 4; i++) {
            float mx = -INFINITY;
            #pragma unroll
            for (int j = 0; j < 4; j++) {
                s[i][j] = s[i][j] * ATT_SCALE + (rv[i] ? m2s[tx * 4 + j] : NEGV);
                mx = fmaxf(mx, s[i][j]);
            }
            rs[i] = mx;
        }
        #pragma unroll
        for (int off = 1; off < 16; off <<= 1) {
            #pragma unroll
            for (int i = 0; i < 4; i++)
                rs[i] = fmaxf(rs[i], __shfl_xor_sync(0xffffffffu, rs[i], off));
        }
        #pragma unroll
        for (int i = 0; i < 4; i++) {
            float mn = fmaxf(m_run[i], rs[i]);
            corr[i] = __expf(m_run[i] - mn);   // exp(-inf)=0 on first tile
            m_run[i] = mn;
            float sum = 0.f;
            #pragma unroll
            for (int j = 0; j < 4; j++) {
                s[i][j] = __expf(s[i][j] - mn);
                sum += s[i][j];
            }
            rs[i] = sum;
        }
        #pragma unroll
        for (int off = 1; off < 16; off <<= 1) {
            #pragma unroll
            for (int i = 0; i < 4; i++)
                rs[i] += __shfl_xor_sync(0xffffffffu, rs[i], off);
        }
        #pragma unroll
        for (int i = 0; i < 4; i++) {
            l_run[i] = l_run[i] * corr[i] + rs[i];
            #pragma unroll
            for (int j = 0; j < 4; j++) o[i][j] *= corr[i];
        }
        #pragma unroll
        for (int i = 0; i < 4; i++)
            *(float4*)&Ps[ty * 4 + i][tx * 4] =
                make_float4(s[i][0], s[i][1], s[i][2], s[i][3]);
        __syncthreads();

        // ---- O += P @ K (v = k) ----
        #pragma unroll 4
        for (int c = 0; c < 64; c += 4) {
            float pf[4][4], kf2[4][4];
            #pragma unroll
            for (int i = 0; i < 4; i++)
                *(float4*)&pf[i][0] = *(const float4*)&Ps[ty * 4 + i][c];
            #pragma unroll
            for (int u = 0; u < 4; u++)
                *(float4*)&kf2[u][0] = *(const float4*)&Kr[c + u][tx * 4];
            #pragma unroll
            for (int u = 0; u < 4; u++)
                #pragma unroll
                for (int i = 0; i < 4; i++)
                    #pragma unroll
                    for (int j = 0; j < 4; j++)
                        o[i][j] += pf[i][u] * kf2[u][j];
        }
    }

    float* Og = g_A + (size_t)(b * SEQ + qt * 64) * DIM + h * HD;
    #pragma unroll
    for (int i = 0; i < 4; i++) {
        float inv = 1.0f / l_run[i];
        float4 v = make_float4(o[i][0] * inv, o[i][1] * inv,
                               o[i][2] * inv, o[i][3] * inv);
        *(float4*)(Og + (size_t)(ty * 4 + i) * DIM + tx * 4) = v;
    }
}

// ---------------------------------------------------------------------------
// Epilogue: x = LN1(attn + modal1); out = LN2(attn + x).  (FFN is dead code.)
// One block per row (512 floats), 128 threads x float4.
// ---------------------------------------------------------------------------
__global__ __launch_bounds__(128) void epilogue_kernel(
    const float* __restrict__ modal1,
    const float* __restrict__ g1, const float* __restrict__ b1,
    const float* __restrict__ g2, const float* __restrict__ b2,
    float* __restrict__ out)
{
    __shared__ float red[2][4];
    const int row = blockIdx.x;
    const int t = threadIdx.x;
    const int lane = t & 31, wid = t >> 5;

    const float4 av = ((const float4*)(g_A    + (size_t)row * DIM))[t];
    const float4 mv = ((const float4*)(modal1 + (size_t)row * DIM))[t];
    float x[4] = {av.x + mv.x, av.y + mv.y, av.z + mv.z, av.w + mv.w};

    float s = x[0] + x[1] + x[2] + x[3];
    float q = x[0]*x[0] + x[1]*x[1] + x[2]*x[2] + x[3]*x[3];
    #pragma unroll
    for (int off = 16; off > 0; off >>= 1) {
        s += __shfl_xor_sync(0xffffffffu, s, off);
        q += __shfl_xor_sync(0xffffffffu, q, off);
    }
    if (lane == 0) { red[0][wid] = s; red[1][wid] = q; }
    __syncthreads();
    s = red[0][0] + red[0][1] + red[0][2] + red[0][3];
    q = red[1][0] + red[1][1] + red[1][2] + red[1][3];
    float mean = s * (1.0f / 512.0f);
    float var  = q * (1.0f / 512.0f) - mean * mean;
    float rstd = rsqrtf(var + 1e-5f);

    const float4 g1f = ((const float4*)g1)[t];
    const float4 b1f = ((const float4*)b1)[t];
    float y[4];
    y[0] = av.x + ((x[0] - mean) * rstd * g1f.x + b1f.x);
    y[1] = av.y + ((x[1] - mean) * rstd * g1f.y + b1f.y);
    y[2] = av.z + ((x[2] - mean) * rstd * g1f.z + b1f.z);
    y[3] = av.w + ((x[3] - mean) * rstd * g1f.w + b1f.w);

    __syncthreads();   // red reuse
    s = y[0] + y[1] + y[2] + y[3];
    q = y[0]*y[0] + y[1]*y[1] + y[2]*y[2] + y[3]*y[3];
    #pragma unroll
    for (int off = 16; off > 0; off >>= 1) {
        s += __shfl_xor_sync(0xffffffffu, s, off);
        q += __shfl_xor_sync(0xffffffffu, q, off);
    }
    if (lane == 0) { red[0][wid] = s; red[1][wid] = q; }
    __syncthreads();
    s = red[0][0] + red[0][1] + red[0][2] + red[0][3];
    q = red[1][0] + red[1][1] + red[1][2] + red[1][3];
    float mean2 = s * (1.0f / 512.0f);
    float var2  = q * (1.0f / 512.0f) - mean2 * mean2;
    float rstd2 = rsqrtf(var2 + 1e-5f);

    const float4 g2f = ((const float4*)g2)[t];
    const float4 b2f = ((const float4*)b2)[t];
    float4 ov = make_float4((y[0] - mean2) * rstd2 * g2f.x + b2f.x,
                            (y[1] - mean2) * rstd2 * g2f.y + b2f.y,
                            (y[2] - mean2) * rstd2 * g2f.z + b2f.z,
                            (y[3] - mean2) * rstd2 * g2f.w + b2f.w);
    ((float4*)(out + (size_t)row * DIM))[t] = ov;
}

// ---------------------------------------------------------------------------
extern "C" void kernel_launch(void* const* d_in, const int* in_sizes, int n_in,
                              void* d_out, int out_size)
{
    const float* modal1 = (const float*)d_in[0];
    const float* modal2 = (const float*)d_in[1];
    const int*   um1    = (const int*)  d_in[2];
    const int*   um2    = (const int*)  d_in[3];
    const float* Wq     = (const float*)d_in[4];
    const float* bq     = (const float*)d_in[5];
    const float* Wkv    = (const float*)d_in[6];
    const float* bkv    = (const float*)d_in[7];
    const float* ln1g   = (const float*)d_in[8];
    const float* ln1b   = (const float*)d_in[9];
    // d_in[10..13] = W1,b1,W2,b2 -> FFN output is discarded by the reference; skipped.
    const float* ln2g   = (const float*)d_in[14];
    const float* ln2b   = (const float*)d_in[15];
    float* out = (float*)d_out;

    cudaFuncSetAttribute(attn_kernel,
                         cudaFuncAttributeMaxDynamicSharedMemorySize, ATT_SMEM);

    dim3 gg(DIM / 128, (BSZ * SEQ) / 128, 2);
    gemm_qkv<<<gg, 256>>>(modal1, modal2, Wq, bq, Wkv, bkv);

    dim3 ga(SEQ / 64, NHEAD, BSZ);
    attn_kernel<<<ga, 256, ATT_SMEM>>>(um1, um2);

    epilogue_kernel<<<BSZ * SEQ, 128>>>(modal1, ln1g, ln1b, ln2g, ln2b, out);
}